// round 12
// baseline (speedup 1.0000x reference)
#include <cuda_runtime.h>
#include <cuda_bf16.h>
#include <cstdint>

#define N_NODES 50000
#define K_NBR   16
#define N_EDGES 200000
#define HID     128
#define FEAT    160
#define CTX     17

// ---------------- scratch (activations packed bf16x2) ----------------
__device__ uint32_t g_featsb[N_NODES * 80];
__device__ uint32_t g_xab[N_NODES * 64];
__device__ uint32_t g_xbb[N_NODES * 64];
__device__ uint32_t g_qkvb[N_NODES * 192];
__device__ uint32_t g_ob[N_NODES * 64];
__device__ int      g_has[N_NODES];
__device__ uint32_t g_uwb[N_NODES * 128];
__device__ float    g_biasuw[256];

// packed bf16x2 weights [col][k/2]
#define WPK_PROJ 0
#define WPK_QKV  10240
#define WPK_WO   (WPK_QKV + 73728)
#define WPK_UW   (WPK_WO + 24576)
#define WPK_TOT  (WPK_UW + 16384)
__device__ uint32_t g_wpk[WPK_TOT];

#define PACK_N   125184
#define PREP_N   (PACK_N + N_NODES * 80 + N_NODES)

__device__ __forceinline__ uint32_t packbf(float lo, float hi) {
    __nv_bfloat162 p = __floats2bfloat162_rn(lo, hi);
    return *reinterpret_cast<uint32_t*>(&p);
}
__device__ __forceinline__ float2 unpk(uint32_t u) {
    __nv_bfloat162 b = *reinterpret_cast<__nv_bfloat162*>(&u);
    return __bfloat1622float2(b);
}
__device__ __forceinline__ float to_tf32(float x) {
    uint32_t u;
    asm("cvt.rna.tf32.f32 %0, %1;" : "=r"(u) : "f"(x));
    return __uint_as_float(u);
}
__device__ __forceinline__ uint32_t smaddr(const void* p) {
    return (uint32_t)__cvta_generic_to_shared(p);
}
// packed f32x2 helpers (Blackwell FFMA2 path)
__device__ __forceinline__ uint64_t upk2(uint32_t u) {   // bf16x2 -> packed f32x2
    uint32_t lo = u << 16, hi = u & 0xffff0000u;
    uint64_t r; asm("mov.b64 %0, {%1,%2};" : "=l"(r) : "r"(lo), "r"(hi)); return r;
}
__device__ __forceinline__ uint64_t pk2f(float a, float b) {
    uint64_t r; asm("mov.b64 %0, {%1,%2};" : "=l"(r) : "f"(a), "f"(b)); return r;
}
__device__ __forceinline__ void fma2(uint64_t& d, uint64_t a, uint64_t b) {
    asm("fma.rn.f32x2 %0, %1, %2, %0;" : "+l"(d) : "l"(a), "l"(b));
}
__device__ __forceinline__ uint64_t mul2(uint64_t a, uint64_t b) {
    uint64_t r; asm("mul.rn.f32x2 %0, %1, %2;" : "=l"(r) : "l"(a), "l"(b)); return r;
}
__device__ __forceinline__ float2 unpk64(uint64_t v) {
    float2 f; asm("mov.b64 {%0,%1}, %2;" : "=f"(f.x), "=f"(f.y) : "l"(v)); return f;
}
__device__ __forceinline__ void ldsm_x4(uint32_t& a0, uint32_t& a1, uint32_t& a2,
                                        uint32_t& a3, uint32_t addr) {
    asm volatile("ldmatrix.sync.aligned.m8n8.x4.shared.b16 {%0,%1,%2,%3}, [%4];"
                 : "=r"(a0), "=r"(a1), "=r"(a2), "=r"(a3) : "r"(addr));
}
__device__ __forceinline__ void ldsm_x2(uint32_t& b0, uint32_t& b1, uint32_t addr) {
    asm volatile("ldmatrix.sync.aligned.m8n8.x2.shared.b16 {%0,%1}, [%2];"
                 : "=r"(b0), "=r"(b1) : "r"(addr));
}
__device__ __forceinline__ void mma_bf16(float c[4], const uint32_t a[4],
                                         uint32_t b0, uint32_t b1) {
    asm volatile(
        "mma.sync.aligned.m16n8k16.row.col.f32.bf16.bf16.f32 "
        "{%0,%1,%2,%3}, {%4,%5,%6,%7}, {%8,%9}, {%0,%1,%2,%3};\n"
        : "+f"(c[0]), "+f"(c[1]), "+f"(c[2]), "+f"(c[3])
        : "r"(a[0]), "r"(a[1]), "r"(a[2]), "r"(a[3]), "r"(b0), "r"(b1));
}
__device__ __forceinline__ void mma_tf32(float c[4], const uint32_t a[4],
                                         uint32_t b0, uint32_t b1) {
    asm volatile(
        "mma.sync.aligned.m16n8k8.row.col.f32.tf32.tf32.f32 "
        "{%0,%1,%2,%3}, {%4,%5,%6,%7}, {%8,%9}, {%0,%1,%2,%3};\n"
        : "+f"(c[0]), "+f"(c[1]), "+f"(c[2]), "+f"(c[3])
        : "r"(a[0]), "r"(a[1]), "r"(a[2]), "r"(a[3]), "r"(b0), "r"(b1));
}

// ---------------- fused prep: weight pack + node feature encode + has_nbr ----------------
__global__ void prep_kernel(const float* __restrict__ proj_W,
                            const float* __restrict__ Wqkv,
                            const float* __restrict__ Wo,
                            const float* __restrict__ eW1,
                            const float* __restrict__ eb1,
                            const int* __restrict__ type_idx,
                            const int* __restrict__ cat_idx,
                            const float* __restrict__ log_deg,
                            const float* __restrict__ type_embed,
                            const float* __restrict__ cat_embed0,
                            const float* __restrict__ cat_embed1,
                            const float* __restrict__ deg_W,
                            const float* __restrict__ deg_b,
                            const int* __restrict__ nbr_mask,
                            uint32_t* __restrict__ wpk,
                            float* __restrict__ biasuw,
                            uint32_t* __restrict__ featsb,
                            int* __restrict__ has)
{
    int i = blockIdx.x * blockDim.x + threadIdx.x;
    if (i < PACK_N) {
        if (i < 10240) {
            int col = i / 80, kp = i - col * 80;
            wpk[WPK_PROJ + i] = packbf(proj_W[(size_t)(2 * kp) * 128 + col],
                                       proj_W[(size_t)(2 * kp + 1) * 128 + col]);
            return;
        }
        i -= 10240;
        if (i < 73728) {
            int l = i / 24576, r = i - l * 24576;
            int col = r / 64, kp = r - col * 64;
            const float* s = Wqkv + (size_t)l * 128 * 384;
            wpk[WPK_QKV + i] = packbf(s[(size_t)(2 * kp) * 384 + col],
                                      s[(size_t)(2 * kp + 1) * 384 + col]);
            return;
        }
        i -= 73728;
        if (i < 24576) {
            int l = i / 8192, r = i - l * 8192;
            int col = r / 64, kp = r - col * 64;
            const float* s = Wo + (size_t)l * 128 * 128;
            wpk[WPK_WO + i] = packbf(s[(size_t)(2 * kp) * 128 + col],
                                     s[(size_t)(2 * kp + 1) * 128 + col]);
            return;
        }
        i -= 24576;
        if (i < 16384) {
            int seg = i >> 13, r = i & 8191;
            int col = r / 64, kp = r - col * 64;
            const float* s = eW1 + (size_t)seg * 128 * 128;
            wpk[WPK_UW + i] = packbf(s[(size_t)(2 * kp) * 128 + col],
                                     s[(size_t)(2 * kp + 1) * 128 + col]);
            return;
        }
        i -= 16384;
        if (i < 256) biasuw[i] = (i < 128) ? eb1[i] : 0.f;
        return;
    }
    i -= PACK_N;
    if (i < N_NODES * 80) {
        int n = i / 80, jp = i - n * 80;
        int j = jp * 2;
        float lo, hi;
        if (j < 64) {
            const float* e = type_embed + type_idx[n] * 64 + j;
            lo = e[0]; hi = e[1];
        } else if (j < 96) {
            const float* e = cat_embed0 + cat_idx[2 * n] * 32 + (j - 64);
            lo = e[0]; hi = e[1];
        } else if (j < 128) {
            const float* e = cat_embed1 + cat_idx[2 * n + 1] * 32 + (j - 96);
            lo = e[0]; hi = e[1];
        } else {
            int jj = j - 128;
            float d = log_deg[n];
            lo = fmaxf(d * deg_W[jj] + deg_b[jj], 0.f);
            hi = fmaxf(d * deg_W[jj + 1] + deg_b[jj + 1], 0.f);
        }
        featsb[i] = packbf(lo, hi);
        return;
    }
    int n = i - N_NODES * 80;
    if (n < N_NODES) {
        int a = 0;
#pragma unroll
        for (int j = 0; j < K_NBR; j++) a |= nbr_mask[n * K_NBR + j];
        has[n] = a ? 1 : 0;
    }
}

// ---------------- bf16 TC GEMM, 128x128 tile (unchanged, 359us config) ----------------
template <int KDIM, int MODE, bool HASBIAS>
__global__ void __launch_bounds__(256, 2)
gemm_bf16(const uint32_t* __restrict__ A, const uint32_t* __restrict__ Wpk,
          const float* __restrict__ bias, uint32_t* __restrict__ out, int ldo,
          int rows, const uint32_t* __restrict__ fbx, const int* __restrict__ fbmask)
{
    constexpr int K2  = KDIM / 2;
    constexpr int K2P = (KDIM == 160) ? 84 : 68;
    constexpr int KQ  = K2 / 4;

    extern __shared__ __align__(16) uint32_t dsm[];
    uint32_t* As = dsm;
    uint32_t* Bs = dsm + 128 * K2P;

    int t = threadIdx.x, lane = t & 31, wid = t >> 5;
    int g = lane >> 2, tig = lane & 3;
    int wm = wid & 3, wn = wid >> 2;
    int row0 = blockIdx.x * 128;
    int colbase = blockIdx.y * 128;

#pragma unroll
    for (int it = 0; it < 128 * KQ / 256; it++) {
        int i = t + it * 256;
        int r = i / KQ, q = (i - r * KQ) * 4;
        int gr = row0 + r;
        uint4 v = make_uint4(0u, 0u, 0u, 0u);
        if (gr < rows) v = *reinterpret_cast<const uint4*>(&A[(size_t)gr * K2 + q]);
        *reinterpret_cast<uint4*>(&As[r * K2P + q]) = v;
    }
#pragma unroll
    for (int it = 0; it < 128 * KQ / 256; it++) {
        int i = t + it * 256;
        int c = i / KQ, q = (i - c * KQ) * 4;
        uint4 v = *reinterpret_cast<const uint4*>(&Wpk[(size_t)(colbase + c) * K2 + q]);
        *reinterpret_cast<uint4*>(&Bs[c * K2P + q]) = v;
    }
    __syncthreads();

    uint32_t aBase = smaddr(As) + ((wm * 32 + (lane & 15)) * K2P + ((lane >> 4) << 2)) * 4;
    uint32_t bBase = smaddr(Bs) + ((wn * 64 + (lane & 7)) * K2P + ((lane & 8) ? 4 : 0)) * 4;

    float acc[2][8][4];
#pragma unroll
    for (int i = 0; i < 2; i++)
#pragma unroll
        for (int j = 0; j < 8; j++)
#pragma unroll
            for (int k = 0; k < 4; k++) acc[i][j][k] = 0.f;

#pragma unroll
    for (int s = 0; s < K2 / 8; s++) {
        uint32_t a[2][4];
        ldsm_x4(a[0][0], a[0][1], a[0][2], a[0][3], aBase + s * 32);
        ldsm_x4(a[1][0], a[1][1], a[1][2], a[1][3], aBase + 16 * K2P * 4 + s * 32);
#pragma unroll
        for (int nt = 0; nt < 8; nt++) {
            uint32_t b0, b1;
            ldsm_x2(b0, b1, bBase + nt * 8 * K2P * 4 + s * 32);
            mma_bf16(acc[0][nt], a[0], b0, b1);
            mma_bf16(acc[1][nt], a[1], b0, b1);
        }
    }

#pragma unroll
    for (int mt = 0; mt < 2; mt++) {
#pragma unroll
        for (int half = 0; half < 2; half++) {
            int gr = row0 + wm * 32 + mt * 16 + g + half * 8;
            if (gr >= rows) continue;
            bool fb = false;
            if (MODE == 2) fb = (fbmask[gr] == 0);
#pragma unroll
            for (int nt = 0; nt < 8; nt++) {
                int col = colbase + wn * 64 + nt * 8 + tig * 2;
                int pair = wn * 32 + nt * 4 + tig;
                float v0 = acc[mt][nt][half * 2 + 0];
                float v1 = acc[mt][nt][half * 2 + 1];
                if (HASBIAS) { v0 += bias[col]; v1 += bias[col + 1]; }
                if (MODE == 2) {
                    if (fb) {
                        float2 f = unpk(fbx[(size_t)gr * 64 + pair]);
                        v0 = f.x; v1 = f.y;
                    }
                    v0 = fmaxf(v0, 0.f);
                    v1 = fmaxf(v1, 0.f);
                }
                out[(size_t)gr * ldo + (colbase >> 1) + pair] = packbf(v0, v1);
            }
        }
    }
}

// ---------------- attention v2: 2 nodes/warp, 16 lanes/node, packed f32x2 math ----------
// lane = half*16 + hl ; node n = 2*warp + half ; lane covers dims hl*8..hl*8+7
// head h = hl>>2 (4 lanes per head) -> reduction = 2 shuffle stages (xor 1, 2)
__global__ void attn_kernel(const uint32_t* __restrict__ qkvb,
                            const int* __restrict__ nbr_idx,
                            const int* __restrict__ nbr_mask,
                            uint32_t* __restrict__ ob)
{
    int w = (blockIdx.x * blockDim.x + threadIdx.x) >> 5;
    int n0 = w * 2;
    if (n0 >= N_NODES) return;
    int lane = threadIdx.x & 31;
    int half = lane >> 4, hl = lane & 15;
    int n = n0 + half;                              // N_NODES even -> always valid
    int p4 = hl * 4;                                // pair offset within 64-pair row

    uint4 qp = *reinterpret_cast<const uint4*>(&qkvb[(size_t)n * 192 + p4]);
    uint64_t q0 = upk2(qp.x), q1 = upk2(qp.y), q2 = upk2(qp.z), q3 = upk2(qp.w);

    int nb = nbr_idx[n * K_NBR + hl];
    int mk = nbr_mask[n * K_NBR + hl];
    unsigned mb = __ballot_sync(0xffffffffu, mk != 0);
    unsigned actm = (((mb >> (half * 16)) & 0xffffu) << 1) | 1u;

    int idxs[CTX];
    float sc[CTX];
#pragma unroll
    for (int c = 0; c < CTX; c++) {
        int id = (c == 0) ? n : __shfl_sync(0xffffffffu, nb, (half << 4) + (c - 1));
        idxs[c] = id;
        uint4 kp = *reinterpret_cast<const uint4*>(&qkvb[(size_t)id * 192 + 64 + p4]);
        uint64_t acc = mul2(q0, upk2(kp.x));
        fma2(acc, q1, upk2(kp.y));
        fma2(acc, q2, upk2(kp.z));
        fma2(acc, q3, upk2(kp.w));
        float2 ap = unpk64(acc);
        float s = ap.x + ap.y;
        s += __shfl_xor_sync(0xffffffffu, s, 1);
        s += __shfl_xor_sync(0xffffffffu, s, 2);
        s *= 0.17677669529663687f;                  // 1/sqrt(32)
        if (c > 0 && !((actm >> c) & 1)) s = -1e9f;
        sc[c] = s;
    }

    float mx = sc[0];
#pragma unroll
    for (int c = 1; c < CTX; c++) mx = fmaxf(mx, sc[c]);
    float den = 0.f;
#pragma unroll
    for (int c = 0; c < CTX; c++) { sc[c] = __expf(sc[c] - mx); den += sc[c]; }
    float inv = 1.f / den;

    uint64_t av0 = 0, av1 = 0, av2 = 0, av3 = 0;
#pragma unroll
    for (int c = 0; c < CTX; c++) {
        uint4 vp = *reinterpret_cast<const uint4*>(&qkvb[(size_t)idxs[c] * 192 + 128 + p4]);
        uint64_t pp = pk2f(sc[c], sc[c]);
        fma2(av0, pp, upk2(vp.x));
        fma2(av1, pp, upk2(vp.y));
        fma2(av2, pp, upk2(vp.z));
        fma2(av3, pp, upk2(vp.w));
    }
    uint64_t iv = pk2f(inv, inv);
    float2 o0 = unpk64(mul2(av0, iv));
    float2 o1 = unpk64(mul2(av1, iv));
    float2 o2 = unpk64(mul2(av2, iv));
    float2 o3 = unpk64(mul2(av3, iv));
    uint4 ov;
    ov.x = packbf(o0.x, o0.y);
    ov.y = packbf(o1.x, o1.y);
    ov.z = packbf(o2.x, o2.y);
    ov.w = packbf(o3.x, o3.y);
    *reinterpret_cast<uint4*>(&ob[(size_t)n * 64 + p4]) = ov;
}

// ---------------- fused edge MLP, tf32 TC phase 2: 64 edges per block (unchanged) --------
__global__ void __launch_bounds__(256)
edge_fused_kernel(const uint32_t* __restrict__ uwb,
                  const int* __restrict__ edges,
                  const float* __restrict__ ef,
                  const float* __restrict__ eW1,
                  const float* __restrict__ eW2,
                  const float* __restrict__ eb2,
                  const float* __restrict__ eW3,
                  const float* __restrict__ eb3,
                  float* __restrict__ out)
{
    extern __shared__ __align__(16) float edsm[];
    float* W2s = edsm;                    // [128][72]
    float* h1s = edsm + 128 * 72;         // [64][132]
    float* part = h1s + 64 * 132;         // [64][2]

    int t = threadIdx.x;
    int lane = t & 31, wid = t >> 5;
    int g = lane >> 2, tig = lane & 3;
    int e0 = blockIdx.x * 64;

#pragma unroll
    for (int it = 0; it < 8; it++) {
        int i = t + it * 256;
        int k = i >> 4, c4 = (i & 15) << 2;
        float4 v = *reinterpret_cast<const float4*>(&eW2[(size_t)k * 64 + c4]);
        W2s[k * 72 + c4 + 0] = to_tf32(v.x);
        W2s[k * 72 + c4 + 1] = to_tf32(v.y);
        W2s[k * 72 + c4 + 2] = to_tf32(v.z);
        W2s[k * 72 + c4 + 3] = to_tf32(v.w);
    }

    const float* wef0 = eW1 + 256 * 128;
    const float* wef1 = eW1 + 257 * 128;
    float4 we0 = *reinterpret_cast<const float4*>(&wef0[lane * 4]);
    float4 we1 = *reinterpret_cast<const float4*>(&wef1[lane * 4]);

#pragma unroll
    for (int ee = 0; ee < 8; ee++) {
        int el = wid * 8 + ee;
        int e = e0 + el;
        int s = edges[2 * e], d = edges[2 * e + 1];
        float f0 = ef[2 * e], f1 = ef[2 * e + 1];
        uint2 up2 = *reinterpret_cast<const uint2*>(&uwb[(size_t)s * 128 + lane * 2]);
        uint2 wp2 = *reinterpret_cast<const uint2*>(&uwb[(size_t)d * 128 + 64 + lane * 2]);
        float2 ua = unpk(up2.x), ub = unpk(up2.y);
        float2 wa = unpk(wp2.x), wb = unpk(wp2.y);
        float4 h;
        h.x = to_tf32(fmaxf(ua.x + wa.x + f0 * we0.x + f1 * we1.x, 0.f));
        h.y = to_tf32(fmaxf(ua.y + wa.y + f0 * we0.y + f1 * we1.y, 0.f));
        h.z = to_tf32(fmaxf(ub.x + wb.x + f0 * we0.z + f1 * we1.z, 0.f));
        h.w = to_tf32(fmaxf(ub.y + wb.y + f0 * we0.w + f1 * we1.w, 0.f));
        *reinterpret_cast<float4*>(&h1s[el * 132 + lane * 4]) = h;
    }
    __syncthreads();

    int rb = (wid & 3) * 16;
    int cb = (wid >> 2) * 32;

    float acc[4][4];
#pragma unroll
    for (int i = 0; i < 4; i++)
#pragma unroll
        for (int j = 0; j < 4; j++) acc[i][j] = 0.f;

#pragma unroll
    for (int kb = 0; kb < 128; kb += 8) {
        uint32_t a[4];
        a[0] = __float_as_uint(h1s[(rb + g) * 132 + kb + tig]);
        a[1] = __float_as_uint(h1s[(rb + g + 8) * 132 + kb + tig]);
        a[2] = __float_as_uint(h1s[(rb + g) * 132 + kb + tig + 4]);
        a[3] = __float_as_uint(h1s[(rb + g + 8) * 132 + kb + tig + 4]);
#pragma unroll
        for (int nt = 0; nt < 4; nt++) {
            int c = cb + nt * 8 + g;
            uint32_t b0 = __float_as_uint(W2s[(kb + tig) * 72 + c]);
            uint32_t b1 = __float_as_uint(W2s[(kb + tig + 4) * 72 + c]);
            mma_tf32(acc[nt], a, b0, b1);
        }
    }

    float pg = 0.f, pg8 = 0.f;
#pragma unroll
    for (int nt = 0; nt < 4; nt++) {
        int col = cb + nt * 8 + tig * 2;
        float b20 = eb2[col], b21 = eb2[col + 1];
        float w30 = eW3[col], w31 = eW3[col + 1];
        pg  += fmaxf(acc[nt][0] + b20, 0.f) * w30 + fmaxf(acc[nt][1] + b21, 0.f) * w31;
        pg8 += fmaxf(acc[nt][2] + b20, 0.f) * w30 + fmaxf(acc[nt][3] + b21, 0.f) * w31;
    }
    pg  += __shfl_xor_sync(0xffffffffu, pg, 1);
    pg  += __shfl_xor_sync(0xffffffffu, pg, 2);
    pg8 += __shfl_xor_sync(0xffffffffu, pg8, 1);
    pg8 += __shfl_xor_sync(0xffffffffu, pg8, 2);
    if (tig == 0) {
        part[(rb + g) * 2 + (wid >> 2)]     = pg;
        part[(rb + 8 + g) * 2 + (wid >> 2)] = pg8;
    }
    __syncthreads();
    if (t < 64) out[e0 + t] = part[t * 2] + part[t * 2 + 1] + eb3[0];
}

// ---------------- launch ----------------
extern "C" void kernel_launch(void* const* d_in, const int* in_sizes, int n_in,
                              void* d_out, int out_size)
{
    (void)in_sizes; (void)n_in; (void)out_size;
    const int*   type_idx   = (const int*)d_in[0];
    const int*   cat_idx    = (const int*)d_in[1];
    const int*   nbr_idx    = (const int*)d_in[2];
    const int*   nbr_mask   = (const int*)d_in[3];
    const int*   edges      = (const int*)d_in[4];
    const float* log_deg    = (const float*)d_in[5];
    const float* edge_feats = (const float*)d_in[6];
    const float* type_embed = (const float*)d_in[7];
    const float* cat_embed0 = (const float*)d_in[8];
    const float* cat_embed1 = (const float*)d_in[9];
    const float* deg_W      = (const float*)d_in[10];
    const float* deg_b      = (const float*)d_in[11];
    const float* proj_W     = (const float*)d_in[12];
    const float* proj_b     = (const float*)d_in[13];
    const float* Wqkv       = (const float*)d_in[14];
    const float* bqkv       = (const float*)d_in[15];
    const float* Wo         = (const float*)d_in[16];
    const float* bo         = (const float*)d_in[17];
    const float* eW1        = (const float*)d_in[18];
    const float* eb1        = (const float*)d_in[19];
    const float* eW2        = (const float*)d_in[20];
    const float* eb2        = (const float*)d_in[21];
    const float* eW3        = (const float*)d_in[22];
    const float* eb3        = (const float*)d_in[23];
    float* out = (float*)d_out;

    uint32_t *featsb, *xab, *xbb, *qkvb, *ob, *uwb, *wpk;
    float* biasuw; int* has;
    cudaGetSymbolAddress((void**)&featsb, g_featsb);
    cudaGetSymbolAddress((void**)&xab, g_xab);
    cudaGetSymbolAddress((void**)&xbb, g_xbb);
    cudaGetSymbolAddress((void**)&qkvb, g_qkvb);
    cudaGetSymbolAddress((void**)&ob, g_ob);
    cudaGetSymbolAddress((void**)&uwb, g_uwb);
    cudaGetSymbolAddress((void**)&has, g_has);
    cudaGetSymbolAddress((void**)&wpk, g_wpk);
    cudaGetSymbolAddress((void**)&biasuw, g_biasuw);

    const int SM128 = 2 * 128 * 68 * 4;
    const int SM160 = 2 * 128 * 84 * 4;
    const int SMEDGE = (128 * 72 + 64 * 132 + 128) * 4;
    cudaFuncSetAttribute(gemm_bf16<160, 0, true>, cudaFuncAttributeMaxDynamicSharedMemorySize, SM160);
    cudaFuncSetAttribute(gemm_bf16<128, 0, true>, cudaFuncAttributeMaxDynamicSharedMemorySize, SM128);
    cudaFuncSetAttribute(gemm_bf16<128, 2, true>, cudaFuncAttributeMaxDynamicSharedMemorySize, SM128);
    cudaFuncSetAttribute(edge_fused_kernel, cudaFuncAttributeMaxDynamicSharedMemorySize, SMEDGE);

    prep_kernel<<<(PREP_N + 255) / 256, 256>>>(
        proj_W, Wqkv, Wo, eW1, eb1,
        type_idx, cat_idx, log_deg, type_embed, cat_embed0, cat_embed1,
        deg_W, deg_b, nbr_mask, wpk, biasuw, featsb, has);

    int gN = (N_NODES + 127) / 128;
    gemm_bf16<160, 0, true><<<gN, 256, SM160>>>(
        featsb, wpk + WPK_PROJ, proj_b, xab, 64, N_NODES, nullptr, nullptr);

    uint32_t* xcur = xab;
    uint32_t* xnxt = xbb;
    for (int l = 0; l < 3; l++) {
        gemm_bf16<128, 0, true><<<dim3(gN, 3), 256, SM128>>>(
            xcur, wpk + WPK_QKV + l * 24576, bqkv + (size_t)l * 384,
            qkvb, 192, N_NODES, nullptr, nullptr);
        attn_kernel<<<(N_NODES / 2 + 7) / 8, 256>>>(qkvb, nbr_idx, nbr_mask, ob);
        gemm_bf16<128, 2, true><<<gN, 256, SM128>>>(
            ob, wpk + WPK_WO + l * 8192, bo + (size_t)l * 128,
            xnxt, 64, N_NODES, xcur, has);
        uint32_t* tmp = xcur; xcur = xnxt; xnxt = tmp;
    }

    gemm_bf16<128, 0, true><<<dim3(gN, 2), 256, SM128>>>(
        xcur, wpk + WPK_UW, biasuw, uwb, 128, N_NODES, nullptr, nullptr);

    edge_fused_kernel<<<(N_EDGES + 63) / 64, 256, SMEDGE>>>(
        uwb, edges, edge_feats, eW1, eW2, eb2, eW3, eb3, out);
}

// round 14
// speedup vs baseline: 1.1193x; 1.1193x over previous
#include <cuda_runtime.h>
#include <cuda_bf16.h>
#include <cstdint>

#define N_NODES 50000
#define K_NBR   16
#define N_EDGES 200000
#define HID     128
#define FEAT    160
#define CTX     17

// ---------------- scratch (activations packed bf16x2) ----------------
__device__ uint32_t g_featsb[N_NODES * 80];
__device__ uint32_t g_xab[N_NODES * 64];
__device__ uint32_t g_xbb[N_NODES * 64];
__device__ uint32_t g_qkvb[N_NODES * 192];
__device__ uint32_t g_ob[N_NODES * 64];
__device__ int      g_has[N_NODES];
__device__ uint32_t g_uwb[N_NODES * 128];
__device__ float    g_biasuw[256];

// packed bf16x2 weights [col][k/2]
#define WPK_PROJ 0
#define WPK_QKV  10240
#define WPK_WO   (WPK_QKV + 73728)
#define WPK_UW   (WPK_WO + 24576)
#define WPK_TOT  (WPK_UW + 16384)
__device__ uint32_t g_wpk[WPK_TOT];

#define PACK_N   125184
#define PREP_N   (PACK_N + N_NODES * 80 + N_NODES)

__device__ __forceinline__ uint32_t packbf(float lo, float hi) {
    __nv_bfloat162 p = __floats2bfloat162_rn(lo, hi);
    return *reinterpret_cast<uint32_t*>(&p);
}
__device__ __forceinline__ float2 unpk(uint32_t u) {
    __nv_bfloat162 b = *reinterpret_cast<__nv_bfloat162*>(&u);
    return __bfloat1622float2(b);
}
__device__ __forceinline__ float to_tf32(float x) {
    uint32_t u;
    asm("cvt.rna.tf32.f32 %0, %1;" : "=r"(u) : "f"(x));
    return __uint_as_float(u);
}
__device__ __forceinline__ uint32_t smaddr(const void* p) {
    return (uint32_t)__cvta_generic_to_shared(p);
}
// packed f32x2 helpers (Blackwell FFMA2 path)
__device__ __forceinline__ uint64_t upk2(uint32_t u) {   // bf16x2 -> packed f32x2
    uint32_t lo = u << 16, hi = u & 0xffff0000u;
    uint64_t r; asm("mov.b64 %0, {%1,%2};" : "=l"(r) : "r"(lo), "r"(hi)); return r;
}
__device__ __forceinline__ uint64_t pk2f(float a, float b) {
    uint64_t r; asm("mov.b64 %0, {%1,%2};" : "=l"(r) : "f"(a), "f"(b)); return r;
}
__device__ __forceinline__ void fma2(uint64_t& d, uint64_t a, uint64_t b) {
    asm("fma.rn.f32x2 %0, %1, %2, %0;" : "+l"(d) : "l"(a), "l"(b));
}
__device__ __forceinline__ uint64_t mul2(uint64_t a, uint64_t b) {
    uint64_t r; asm("mul.rn.f32x2 %0, %1, %2;" : "=l"(r) : "l"(a), "l"(b)); return r;
}
__device__ __forceinline__ float2 unpk64(uint64_t v) {
    float2 f; asm("mov.b64 {%0,%1}, %2;" : "=f"(f.x), "=f"(f.y) : "l"(v)); return f;
}
__device__ __forceinline__ void ldsm_x4(uint32_t& a0, uint32_t& a1, uint32_t& a2,
                                        uint32_t& a3, uint32_t addr) {
    asm volatile("ldmatrix.sync.aligned.m8n8.x4.shared.b16 {%0,%1,%2,%3}, [%4];"
                 : "=r"(a0), "=r"(a1), "=r"(a2), "=r"(a3) : "r"(addr));
}
__device__ __forceinline__ void ldsm_x2(uint32_t& b0, uint32_t& b1, uint32_t addr) {
    asm volatile("ldmatrix.sync.aligned.m8n8.x2.shared.b16 {%0,%1}, [%2];"
                 : "=r"(b0), "=r"(b1) : "r"(addr));
}
__device__ __forceinline__ void mma_bf16(float c[4], const uint32_t a[4],
                                         uint32_t b0, uint32_t b1) {
    asm volatile(
        "mma.sync.aligned.m16n8k16.row.col.f32.bf16.bf16.f32 "
        "{%0,%1,%2,%3}, {%4,%5,%6,%7}, {%8,%9}, {%0,%1,%2,%3};\n"
        : "+f"(c[0]), "+f"(c[1]), "+f"(c[2]), "+f"(c[3])
        : "r"(a[0]), "r"(a[1]), "r"(a[2]), "r"(a[3]), "r"(b0), "r"(b1));
}
__device__ __forceinline__ void mma_tf32(float c[4], const uint32_t a[4],
                                         uint32_t b0, uint32_t b1) {
    asm volatile(
        "mma.sync.aligned.m16n8k8.row.col.f32.tf32.tf32.f32 "
        "{%0,%1,%2,%3}, {%4,%5,%6,%7}, {%8,%9}, {%0,%1,%2,%3};\n"
        : "+f"(c[0]), "+f"(c[1]), "+f"(c[2]), "+f"(c[3])
        : "r"(a[0]), "r"(a[1]), "r"(a[2]), "r"(a[3]), "r"(b0), "r"(b1));
}

// ---------------- fused prep: weight pack + node feature encode + has_nbr ----------------
__global__ void prep_kernel(const float* __restrict__ proj_W,
                            const float* __restrict__ Wqkv,
                            const float* __restrict__ Wo,
                            const float* __restrict__ eW1,
                            const float* __restrict__ eb1,
                            const int* __restrict__ type_idx,
                            const int* __restrict__ cat_idx,
                            const float* __restrict__ log_deg,
                            const float* __restrict__ type_embed,
                            const float* __restrict__ cat_embed0,
                            const float* __restrict__ cat_embed1,
                            const float* __restrict__ deg_W,
                            const float* __restrict__ deg_b,
                            const int* __restrict__ nbr_mask,
                            uint32_t* __restrict__ wpk,
                            float* __restrict__ biasuw,
                            uint32_t* __restrict__ featsb,
                            int* __restrict__ has)
{
    int i = blockIdx.x * blockDim.x + threadIdx.x;
    if (i < PACK_N) {
        if (i < 10240) {
            int col = i / 80, kp = i - col * 80;
            wpk[WPK_PROJ + i] = packbf(proj_W[(size_t)(2 * kp) * 128 + col],
                                       proj_W[(size_t)(2 * kp + 1) * 128 + col]);
            return;
        }
        i -= 10240;
        if (i < 73728) {
            int l = i / 24576, r = i - l * 24576;
            int col = r / 64, kp = r - col * 64;
            const float* s = Wqkv + (size_t)l * 128 * 384;
            wpk[WPK_QKV + i] = packbf(s[(size_t)(2 * kp) * 384 + col],
                                      s[(size_t)(2 * kp + 1) * 384 + col]);
            return;
        }
        i -= 73728;
        if (i < 24576) {
            int l = i / 8192, r = i - l * 8192;
            int col = r / 64, kp = r - col * 64;
            const float* s = Wo + (size_t)l * 128 * 128;
            wpk[WPK_WO + i] = packbf(s[(size_t)(2 * kp) * 128 + col],
                                     s[(size_t)(2 * kp + 1) * 128 + col]);
            return;
        }
        i -= 24576;
        if (i < 16384) {
            int seg = i >> 13, r = i & 8191;
            int col = r / 64, kp = r - col * 64;
            const float* s = eW1 + (size_t)seg * 128 * 128;
            wpk[WPK_UW + i] = packbf(s[(size_t)(2 * kp) * 128 + col],
                                     s[(size_t)(2 * kp + 1) * 128 + col]);
            return;
        }
        i -= 16384;
        if (i < 256) biasuw[i] = (i < 128) ? eb1[i] : 0.f;
        return;
    }
    i -= PACK_N;
    if (i < N_NODES * 80) {
        int n = i / 80, jp = i - n * 80;
        int j = jp * 2;
        float lo, hi;
        if (j < 64) {
            const float* e = type_embed + type_idx[n] * 64 + j;
            lo = e[0]; hi = e[1];
        } else if (j < 96) {
            const float* e = cat_embed0 + cat_idx[2 * n] * 32 + (j - 64);
            lo = e[0]; hi = e[1];
        } else if (j < 128) {
            const float* e = cat_embed1 + cat_idx[2 * n + 1] * 32 + (j - 96);
            lo = e[0]; hi = e[1];
        } else {
            int jj = j - 128;
            float d = log_deg[n];
            lo = fmaxf(d * deg_W[jj] + deg_b[jj], 0.f);
            hi = fmaxf(d * deg_W[jj + 1] + deg_b[jj + 1], 0.f);
        }
        featsb[i] = packbf(lo, hi);
        return;
    }
    int n = i - N_NODES * 80;
    if (n < N_NODES) {
        int a = 0;
#pragma unroll
        for (int j = 0; j < K_NBR; j++) a |= nbr_mask[n * K_NBR + j];
        has[n] = a ? 1 : 0;
    }
}

// ---------------- bf16 TC GEMM, 128x128 tile (unchanged, 359us config) ----------------
template <int KDIM, int MODE, bool HASBIAS>
__global__ void __launch_bounds__(256, 2)
gemm_bf16(const uint32_t* __restrict__ A, const uint32_t* __restrict__ Wpk,
          const float* __restrict__ bias, uint32_t* __restrict__ out, int ldo,
          int rows, const uint32_t* __restrict__ fbx, const int* __restrict__ fbmask)
{
    constexpr int K2  = KDIM / 2;
    constexpr int K2P = (KDIM == 160) ? 84 : 68;
    constexpr int KQ  = K2 / 4;

    extern __shared__ __align__(16) uint32_t dsm[];
    uint32_t* As = dsm;
    uint32_t* Bs = dsm + 128 * K2P;

    int t = threadIdx.x, lane = t & 31, wid = t >> 5;
    int g = lane >> 2, tig = lane & 3;
    int wm = wid & 3, wn = wid >> 2;
    int row0 = blockIdx.x * 128;
    int colbase = blockIdx.y * 128;

#pragma unroll
    for (int it = 0; it < 128 * KQ / 256; it++) {
        int i = t + it * 256;
        int r = i / KQ, q = (i - r * KQ) * 4;
        int gr = row0 + r;
        uint4 v = make_uint4(0u, 0u, 0u, 0u);
        if (gr < rows) v = *reinterpret_cast<const uint4*>(&A[(size_t)gr * K2 + q]);
        *reinterpret_cast<uint4*>(&As[r * K2P + q]) = v;
    }
#pragma unroll
    for (int it = 0; it < 128 * KQ / 256; it++) {
        int i = t + it * 256;
        int c = i / KQ, q = (i - c * KQ) * 4;
        uint4 v = *reinterpret_cast<const uint4*>(&Wpk[(size_t)(colbase + c) * K2 + q]);
        *reinterpret_cast<uint4*>(&Bs[c * K2P + q]) = v;
    }
    __syncthreads();

    uint32_t aBase = smaddr(As) + ((wm * 32 + (lane & 15)) * K2P + ((lane >> 4) << 2)) * 4;
    uint32_t bBase = smaddr(Bs) + ((wn * 64 + (lane & 7)) * K2P + ((lane & 8) ? 4 : 0)) * 4;

    float acc[2][8][4];
#pragma unroll
    for (int i = 0; i < 2; i++)
#pragma unroll
        for (int j = 0; j < 8; j++)
#pragma unroll
            for (int k = 0; k < 4; k++) acc[i][j][k] = 0.f;

#pragma unroll
    for (int s = 0; s < K2 / 8; s++) {
        uint32_t a[2][4];
        ldsm_x4(a[0][0], a[0][1], a[0][2], a[0][3], aBase + s * 32);
        ldsm_x4(a[1][0], a[1][1], a[1][2], a[1][3], aBase + 16 * K2P * 4 + s * 32);
#pragma unroll
        for (int nt = 0; nt < 8; nt++) {
            uint32_t b0, b1;
            ldsm_x2(b0, b1, bBase + nt * 8 * K2P * 4 + s * 32);
            mma_bf16(acc[0][nt], a[0], b0, b1);
            mma_bf16(acc[1][nt], a[1], b0, b1);
        }
    }

#pragma unroll
    for (int mt = 0; mt < 2; mt++) {
#pragma unroll
        for (int half = 0; half < 2; half++) {
            int gr = row0 + wm * 32 + mt * 16 + g + half * 8;
            if (gr >= rows) continue;
            bool fb = false;
            if (MODE == 2) fb = (fbmask[gr] == 0);
#pragma unroll
            for (int nt = 0; nt < 8; nt++) {
                int col = colbase + wn * 64 + nt * 8 + tig * 2;
                int pair = wn * 32 + nt * 4 + tig;
                float v0 = acc[mt][nt][half * 2 + 0];
                float v1 = acc[mt][nt][half * 2 + 1];
                if (HASBIAS) { v0 += bias[col]; v1 += bias[col + 1]; }
                if (MODE == 2) {
                    if (fb) {
                        float2 f = unpk(fbx[(size_t)gr * 64 + pair]);
                        v0 = f.x; v1 = f.y;
                    }
                    v0 = fmaxf(v0, 0.f);
                    v1 = fmaxf(v1, 0.f);
                }
                out[(size_t)gr * ldo + (colbase >> 1) + pair] = packbf(v0, v1);
            }
        }
    }
}

// ---------------- attention v3b: one warp per node, ctx split across half-warps ----------
// lane = half*16 + hl; lane covers dims hl*8..hl*8+7 (uint4 = 4 bf16x2 pairs)
// half 0: ctx 0..8 ; half 1: ctx 8..16 (ctx 8 dup, forced inactive in half 1).
// FIX vs R13: shfl executed unconditionally by ALL lanes (per-lane src index).
__global__ void attn_kernel(const uint32_t* __restrict__ qkvb,
                            const int* __restrict__ nbr_idx,
                            const int* __restrict__ nbr_mask,
                            uint32_t* __restrict__ ob)
{
    int n = (blockIdx.x * blockDim.x + threadIdx.x) >> 5;
    if (n >= N_NODES) return;
    int lane = threadIdx.x & 31;
    int half = lane >> 4, hl = lane & 15;
    int p4 = hl * 4;

    uint4 qp = *reinterpret_cast<const uint4*>(&qkvb[(size_t)n * 192 + p4]);
    uint64_t q0 = upk2(qp.x), q1 = upk2(qp.y), q2 = upk2(qp.z), q3 = upk2(qp.w);

    int nb = 0, mk = 0;
    if (lane < 16) {
        nb = nbr_idx[n * K_NBR + lane];
        mk = nbr_mask[n * K_NBR + lane];
    }
    unsigned mb = __ballot_sync(0xffffffffu, (lane < 16) && mk);
    unsigned actm = (mb << 1) | 1u;           // bit c: ctx c active (ctx0 self)

    int cbase = half * 8;                     // 0 or 8
    int idxs[9];
    float sc[9];
#pragma unroll
    for (int j = 0; j < 9; j++) {
        int c = cbase + j;
        int src = (c == 0) ? 0 : (c - 1);     // per-lane src; shfl executed by ALL lanes
        int nbj = __shfl_sync(0xffffffffu, nb, src);
        int id = (c == 0) ? n : nbj;
        idxs[j] = id;
        uint4 kp = *reinterpret_cast<const uint4*>(&qkvb[(size_t)id * 192 + 64 + p4]);
        uint64_t acc = mul2(q0, upk2(kp.x));
        fma2(acc, q1, upk2(kp.y));
        fma2(acc, q2, upk2(kp.z));
        fma2(acc, q3, upk2(kp.w));
        float2 ap = unpk64(acc);
        float s = ap.x + ap.y;
        s += __shfl_xor_sync(0xffffffffu, s, 1);
        s += __shfl_xor_sync(0xffffffffu, s, 2);
        s *= 0.17677669529663687f;            // 1/sqrt(32)
        bool on = ((actm >> c) & 1) && !(half == 1 && j == 0);
        if (!on) s = -1e9f;
        sc[j] = s;
    }

    // softmax across both halves (lane hl pairs with lane hl+16, same head)
    float mx = sc[0];
#pragma unroll
    for (int j = 1; j < 9; j++) mx = fmaxf(mx, sc[j]);
    mx = fmaxf(mx, __shfl_xor_sync(0xffffffffu, mx, 16));
    float den = 0.f;
#pragma unroll
    for (int j = 0; j < 9; j++) { sc[j] = __expf(sc[j] - mx); den += sc[j]; }
    den += __shfl_xor_sync(0xffffffffu, den, 16);
    float inv = 1.f / den;

    uint64_t av0 = 0, av1 = 0, av2 = 0, av3 = 0;
#pragma unroll
    for (int j = 0; j < 9; j++) {
        uint4 vp = *reinterpret_cast<const uint4*>(&qkvb[(size_t)idxs[j] * 192 + 128 + p4]);
        uint64_t pp = pk2f(sc[j], sc[j]);
        fma2(av0, pp, upk2(vp.x));
        fma2(av1, pp, upk2(vp.y));
        fma2(av2, pp, upk2(vp.z));
        fma2(av3, pp, upk2(vp.w));
    }
    // combine halves
    float2 a0 = unpk64(av0), a1 = unpk64(av1), a2 = unpk64(av2), a3 = unpk64(av3);
    a0.x += __shfl_xor_sync(0xffffffffu, a0.x, 16);
    a0.y += __shfl_xor_sync(0xffffffffu, a0.y, 16);
    a1.x += __shfl_xor_sync(0xffffffffu, a1.x, 16);
    a1.y += __shfl_xor_sync(0xffffffffu, a1.y, 16);
    a2.x += __shfl_xor_sync(0xffffffffu, a2.x, 16);
    a2.y += __shfl_xor_sync(0xffffffffu, a2.y, 16);
    a3.x += __shfl_xor_sync(0xffffffffu, a3.x, 16);
    a3.y += __shfl_xor_sync(0xffffffffu, a3.y, 16);

    if (half == 0) {
        uint4 ov;
        ov.x = packbf(a0.x * inv, a0.y * inv);
        ov.y = packbf(a1.x * inv, a1.y * inv);
        ov.z = packbf(a2.x * inv, a2.y * inv);
        ov.w = packbf(a3.x * inv, a3.y * inv);
        *reinterpret_cast<uint4*>(&ob[(size_t)n * 64 + p4]) = ov;
    }
}

// ---------------- fused edge MLP, tf32 TC phase 2: 64 edges per block (unchanged) --------
__global__ void __launch_bounds__(256)
edge_fused_kernel(const uint32_t* __restrict__ uwb,
                  const int* __restrict__ edges,
                  const float* __restrict__ ef,
                  const float* __restrict__ eW1,
                  const float* __restrict__ eW2,
                  const float* __restrict__ eb2,
                  const float* __restrict__ eW3,
                  const float* __restrict__ eb3,
                  float* __restrict__ out)
{
    extern __shared__ __align__(16) float edsm[];
    float* W2s = edsm;                    // [128][72]
    float* h1s = edsm + 128 * 72;         // [64][132]
    float* part = h1s + 64 * 132;         // [64][2]

    int t = threadIdx.x;
    int lane = t & 31, wid = t >> 5;
    int g = lane >> 2, tig = lane & 3;
    int e0 = blockIdx.x * 64;

#pragma unroll
    for (int it = 0; it < 8; it++) {
        int i = t + it * 256;
        int k = i >> 4, c4 = (i & 15) << 2;
        float4 v = *reinterpret_cast<const float4*>(&eW2[(size_t)k * 64 + c4]);
        W2s[k * 72 + c4 + 0] = to_tf32(v.x);
        W2s[k * 72 + c4 + 1] = to_tf32(v.y);
        W2s[k * 72 + c4 + 2] = to_tf32(v.z);
        W2s[k * 72 + c4 + 3] = to_tf32(v.w);
    }

    const float* wef0 = eW1 + 256 * 128;
    const float* wef1 = eW1 + 257 * 128;
    float4 we0 = *reinterpret_cast<const float4*>(&wef0[lane * 4]);
    float4 we1 = *reinterpret_cast<const float4*>(&wef1[lane * 4]);

#pragma unroll
    for (int ee = 0; ee < 8; ee++) {
        int el = wid * 8 + ee;
        int e = e0 + el;
        int s = edges[2 * e], d = edges[2 * e + 1];
        float f0 = ef[2 * e], f1 = ef[2 * e + 1];
        uint2 up2 = *reinterpret_cast<const uint2*>(&uwb[(size_t)s * 128 + lane * 2]);
        uint2 wp2 = *reinterpret_cast<const uint2*>(&uwb[(size_t)d * 128 + 64 + lane * 2]);
        float2 ua = unpk(up2.x), ub = unpk(up2.y);
        float2 wa = unpk(wp2.x), wb = unpk(wp2.y);
        float4 h;
        h.x = to_tf32(fmaxf(ua.x + wa.x + f0 * we0.x + f1 * we1.x, 0.f));
        h.y = to_tf32(fmaxf(ua.y + wa.y + f0 * we0.y + f1 * we1.y, 0.f));
        h.z = to_tf32(fmaxf(ub.x + wb.x + f0 * we0.z + f1 * we1.z, 0.f));
        h.w = to_tf32(fmaxf(ub.y + wb.y + f0 * we0.w + f1 * we1.w, 0.f));
        *reinterpret_cast<float4*>(&h1s[el * 132 + lane * 4]) = h;
    }
    __syncthreads();

    int rb = (wid & 3) * 16;
    int cb = (wid >> 2) * 32;

    float acc[4][4];
#pragma unroll
    for (int i = 0; i < 4; i++)
#pragma unroll
        for (int j = 0; j < 4; j++) acc[i][j] = 0.f;

#pragma unroll
    for (int kb = 0; kb < 128; kb += 8) {
        uint32_t a[4];
        a[0] = __float_as_uint(h1s[(rb + g) * 132 + kb + tig]);
        a[1] = __float_as_uint(h1s[(rb + g + 8) * 132 + kb + tig]);
        a[2] = __float_as_uint(h1s[(rb + g) * 132 + kb + tig + 4]);
        a[3] = __float_as_uint(h1s[(rb + g + 8) * 132 + kb + tig + 4]);
#pragma unroll
        for (int nt = 0; nt < 4; nt++) {
            int c = cb + nt * 8 + g;
            uint32_t b0 = __float_as_uint(W2s[(kb + tig) * 72 + c]);
            uint32_t b1 = __float_as_uint(W2s[(kb + tig + 4) * 72 + c]);
            mma_tf32(acc[nt], a, b0, b1);
        }
    }

    float pg = 0.f, pg8 = 0.f;
#pragma unroll
    for (int nt = 0; nt < 4; nt++) {
        int col = cb + nt * 8 + tig * 2;
        float b20 = eb2[col], b21 = eb2[col + 1];
        float w30 = eW3[col], w31 = eW3[col + 1];
        pg  += fmaxf(acc[nt][0] + b20, 0.f) * w30 + fmaxf(acc[nt][1] + b21, 0.f) * w31;
        pg8 += fmaxf(acc[nt][2] + b20, 0.f) * w30 + fmaxf(acc[nt][3] + b21, 0.f) * w31;
    }
    pg  += __shfl_xor_sync(0xffffffffu, pg, 1);
    pg  += __shfl_xor_sync(0xffffffffu, pg, 2);
    pg8 += __shfl_xor_sync(0xffffffffu, pg8, 1);
    pg8 += __shfl_xor_sync(0xffffffffu, pg8, 2);
    if (tig == 0) {
        part[(rb + g) * 2 + (wid >> 2)]     = pg;
        part[(rb + 8 + g) * 2 + (wid >> 2)] = pg8;
    }
    __syncthreads();
    if (t < 64) out[e0 + t] = part[t * 2] + part[t * 2 + 1] + eb3[0];
}

// ---------------- launch ----------------
extern "C" void kernel_launch(void* const* d_in, const int* in_sizes, int n_in,
                              void* d_out, int out_size)
{
    (void)in_sizes; (void)n_in; (void)out_size;
    const int*   type_idx   = (const int*)d_in[0];
    const int*   cat_idx    = (const int*)d_in[1];
    const int*   nbr_idx    = (const int*)d_in[2];
    const int*   nbr_mask   = (const int*)d_in[3];
    const int*   edges      = (const int*)d_in[4];
    const float* log_deg    = (const float*)d_in[5];
    const float* edge_feats = (const float*)d_in[6];
    const float* type_embed = (const float*)d_in[7];
    const float* cat_embed0 = (const float*)d_in[8];
    const float* cat_embed1 = (const float*)d_in[9];
    const float* deg_W      = (const float*)d_in[10];
    const float* deg_b      = (const float*)d_in[11];
    const float* proj_W     = (const float*)d_in[12];
    const float* proj_b     = (const float*)d_in[13];
    const float* Wqkv       = (const float*)d_in[14];
    const float* bqkv       = (const float*)d_in[15];
    const float* Wo         = (const float*)d_in[16];
    const float* bo         = (const float*)d_in[17];
    const float* eW1        = (const float*)d_in[18];
    const float* eb1        = (const float*)d_in[19];
    const float* eW2        = (const float*)d_in[20];
    const float* eb2        = (const float*)d_in[21];
    const float* eW3        = (const float*)d_in[22];
    const float* eb3        = (const float*)d_in[23];
    float* out = (float*)d_out;

    uint32_t *featsb, *xab, *xbb, *qkvb, *ob, *uwb, *wpk;
    float* biasuw; int* has;
    cudaGetSymbolAddress((void**)&featsb, g_featsb);
    cudaGetSymbolAddress((void**)&xab, g_xab);
    cudaGetSymbolAddress((void**)&xbb, g_xbb);
    cudaGetSymbolAddress((void**)&qkvb, g_qkvb);
    cudaGetSymbolAddress((void**)&ob, g_ob);
    cudaGetSymbolAddress((void**)&uwb, g_uwb);
    cudaGetSymbolAddress((void**)&has, g_has);
    cudaGetSymbolAddress((void**)&wpk, g_wpk);
    cudaGetSymbolAddress((void**)&biasuw, g_biasuw);

    const int SM128 = 2 * 128 * 68 * 4;
    const int SM160 = 2 * 128 * 84 * 4;
    const int SMEDGE = (128 * 72 + 64 * 132 + 128) * 4;
    cudaFuncSetAttribute(gemm_bf16<160, 0, true>, cudaFuncAttributeMaxDynamicSharedMemorySize, SM160);
    cudaFuncSetAttribute(gemm_bf16<128, 0, true>, cudaFuncAttributeMaxDynamicSharedMemorySize, SM128);
    cudaFuncSetAttribute(gemm_bf16<128, 2, true>, cudaFuncAttributeMaxDynamicSharedMemorySize, SM128);
    cudaFuncSetAttribute(edge_fused_kernel, cudaFuncAttributeMaxDynamicSharedMemorySize, SMEDGE);

    prep_kernel<<<(PREP_N + 255) / 256, 256>>>(
        proj_W, Wqkv, Wo, eW1, eb1,
        type_idx, cat_idx, log_deg, type_embed, cat_embed0, cat_embed1,
        deg_W, deg_b, nbr_mask, wpk, biasuw, featsb, has);

    int gN = (N_NODES + 127) / 128;
    gemm_bf16<160, 0, true><<<gN, 256, SM160>>>(
        featsb, wpk + WPK_PROJ, proj_b, xab, 64, N_NODES, nullptr, nullptr);

    uint32_t* xcur = xab;
    uint32_t* xnxt = xbb;
    for (int l = 0; l < 3; l++) {
        gemm_bf16<128, 0, true><<<dim3(gN, 3), 256, SM128>>>(
            xcur, wpk + WPK_QKV + l * 24576, bqkv + (size_t)l * 384,
            qkvb, 192, N_NODES, nullptr, nullptr);
        attn_kernel<<<(N_NODES + 7) / 8, 256>>>(qkvb, nbr_idx, nbr_mask, ob);
        gemm_bf16<128, 2, true><<<gN, 256, SM128>>>(
            ob, wpk + WPK_WO + l * 8192, bo + (size_t)l * 128,
            xnxt, 64, N_NODES, xcur, has);
        uint32_t* tmp = xcur; xcur = xnxt; xnxt = tmp;
    }

    gemm_bf16<128, 0, true><<<dim3(gN, 2), 256, SM128>>>(
        xcur, wpk + WPK_UW, biasuw, uwb, 128, N_NODES, nullptr, nullptr);

    edge_fused_kernel<<<(N_EDGES + 63) / 64, 256, SMEDGE>>>(
        uwb, edges, edge_feats, eW1, eW2, eb2, eW3, eb3, out);
}

// round 15
// speedup vs baseline: 1.1226x; 1.0030x over previous
#include <cuda_runtime.h>
#include <cuda_bf16.h>
#include <cstdint>

#define N_NODES 50000
#define K_NBR   16
#define N_EDGES 200000
#define HID     128
#define FEAT    160
#define CTX     17

// ---------------- scratch (activations packed bf16x2) ----------------
__device__ uint32_t g_featsb[N_NODES * 80];
__device__ uint32_t g_xab[N_NODES * 64];
__device__ uint32_t g_xbb[N_NODES * 64];
__device__ uint32_t g_qkvb[N_NODES * 192];
__device__ uint32_t g_ob[N_NODES * 64];
__device__ int      g_has[N_NODES];
__device__ uint32_t g_uwb[N_NODES * 128];
__device__ float    g_biasuw[256];

// packed bf16x2 weights [col][k/2]
#define WPK_PROJ 0
#define WPK_QKV  10240
#define WPK_WO   (WPK_QKV + 73728)
#define WPK_UW   (WPK_WO + 24576)
#define WPK_TOT  (WPK_UW + 16384)
__device__ uint32_t g_wpk[WPK_TOT];

#define PACK_N   125184
#define PREP_N   (PACK_N + N_NODES * 80 + N_NODES)

__device__ __forceinline__ uint32_t packbf(float lo, float hi) {
    __nv_bfloat162 p = __floats2bfloat162_rn(lo, hi);
    return *reinterpret_cast<uint32_t*>(&p);
}
__device__ __forceinline__ float2 unpk(uint32_t u) {
    __nv_bfloat162 b = *reinterpret_cast<__nv_bfloat162*>(&u);
    return __bfloat1622float2(b);
}
__device__ __forceinline__ float to_tf32(float x) {
    uint32_t u;
    asm("cvt.rna.tf32.f32 %0, %1;" : "=r"(u) : "f"(x));
    return __uint_as_float(u);
}
__device__ __forceinline__ uint32_t smaddr(const void* p) {
    return (uint32_t)__cvta_generic_to_shared(p);
}
// packed f32x2 helpers (Blackwell FFMA2 path)
__device__ __forceinline__ uint64_t upk2(uint32_t u) {   // bf16x2 -> packed f32x2
    uint32_t lo = u << 16, hi = u & 0xffff0000u;
    uint64_t r; asm("mov.b64 %0, {%1,%2};" : "=l"(r) : "r"(lo), "r"(hi)); return r;
}
__device__ __forceinline__ uint64_t pk2f(float a, float b) {
    uint64_t r; asm("mov.b64 %0, {%1,%2};" : "=l"(r) : "f"(a), "f"(b)); return r;
}
__device__ __forceinline__ void fma2(uint64_t& d, uint64_t a, uint64_t b) {
    asm("fma.rn.f32x2 %0, %1, %2, %0;" : "+l"(d) : "l"(a), "l"(b));
}
__device__ __forceinline__ uint64_t mul2(uint64_t a, uint64_t b) {
    uint64_t r; asm("mul.rn.f32x2 %0, %1, %2;" : "=l"(r) : "l"(a), "l"(b)); return r;
}
__device__ __forceinline__ float2 unpk64(uint64_t v) {
    float2 f; asm("mov.b64 {%0,%1}, %2;" : "=f"(f.x), "=f"(f.y) : "l"(v)); return f;
}
__device__ __forceinline__ void ldsm_x4(uint32_t& a0, uint32_t& a1, uint32_t& a2,
                                        uint32_t& a3, uint32_t addr) {
    asm volatile("ldmatrix.sync.aligned.m8n8.x4.shared.b16 {%0,%1,%2,%3}, [%4];"
                 : "=r"(a0), "=r"(a1), "=r"(a2), "=r"(a3) : "r"(addr));
}
__device__ __forceinline__ void mma_bf16(float c[4], const uint32_t a[4],
                                         uint32_t b0, uint32_t b1) {
    asm volatile(
        "mma.sync.aligned.m16n8k16.row.col.f32.bf16.bf16.f32 "
        "{%0,%1,%2,%3}, {%4,%5,%6,%7}, {%8,%9}, {%0,%1,%2,%3};\n"
        : "+f"(c[0]), "+f"(c[1]), "+f"(c[2]), "+f"(c[3])
        : "r"(a[0]), "r"(a[1]), "r"(a[2]), "r"(a[3]), "r"(b0), "r"(b1));
}
__device__ __forceinline__ void mma_tf32(float c[4], const uint32_t a[4],
                                         uint32_t b0, uint32_t b1) {
    asm volatile(
        "mma.sync.aligned.m16n8k8.row.col.f32.tf32.tf32.f32 "
        "{%0,%1,%2,%3}, {%4,%5,%6,%7}, {%8,%9}, {%0,%1,%2,%3};\n"
        : "+f"(c[0]), "+f"(c[1]), "+f"(c[2]), "+f"(c[3])
        : "r"(a[0]), "r"(a[1]), "r"(a[2]), "r"(a[3]), "r"(b0), "r"(b1));
}

// ---------------- fused prep: weight pack + node feature encode + has_nbr ----------------
__global__ void prep_kernel(const float* __restrict__ proj_W,
                            const float* __restrict__ Wqkv,
                            const float* __restrict__ Wo,
                            const float* __restrict__ eW1,
                            const float* __restrict__ eb1,
                            const int* __restrict__ type_idx,
                            const int* __restrict__ cat_idx,
                            const float* __restrict__ log_deg,
                            const float* __restrict__ type_embed,
                            const float* __restrict__ cat_embed0,
                            const float* __restrict__ cat_embed1,
                            const float* __restrict__ deg_W,
                            const float* __restrict__ deg_b,
                            const int* __restrict__ nbr_mask,
                            uint32_t* __restrict__ wpk,
                            float* __restrict__ biasuw,
                            uint32_t* __restrict__ featsb,
                            int* __restrict__ has)
{
    int i = blockIdx.x * blockDim.x + threadIdx.x;
    if (i < PACK_N) {
        if (i < 10240) {
            int col = i / 80, kp = i - col * 80;
            wpk[WPK_PROJ + i] = packbf(proj_W[(size_t)(2 * kp) * 128 + col],
                                       proj_W[(size_t)(2 * kp + 1) * 128 + col]);
            return;
        }
        i -= 10240;
        if (i < 73728) {
            int l = i / 24576, r = i - l * 24576;
            int col = r / 64, kp = r - col * 64;
            const float* s = Wqkv + (size_t)l * 128 * 384;
            wpk[WPK_QKV + i] = packbf(s[(size_t)(2 * kp) * 384 + col],
                                      s[(size_t)(2 * kp + 1) * 384 + col]);
            return;
        }
        i -= 73728;
        if (i < 24576) {
            int l = i / 8192, r = i - l * 8192;
            int col = r / 64, kp = r - col * 64;
            const float* s = Wo + (size_t)l * 128 * 128;
            wpk[WPK_WO + i] = packbf(s[(size_t)(2 * kp) * 128 + col],
                                     s[(size_t)(2 * kp + 1) * 128 + col]);
            return;
        }
        i -= 24576;
        if (i < 16384) {
            int seg = i >> 13, r = i & 8191;
            int col = r / 64, kp = r - col * 64;
            const float* s = eW1 + (size_t)seg * 128 * 128;
            wpk[WPK_UW + i] = packbf(s[(size_t)(2 * kp) * 128 + col],
                                     s[(size_t)(2 * kp + 1) * 128 + col]);
            return;
        }
        i -= 16384;
        if (i < 256) biasuw[i] = (i < 128) ? eb1[i] : 0.f;
        return;
    }
    i -= PACK_N;
    if (i < N_NODES * 80) {
        int n = i / 80, jp = i - n * 80;
        int j = jp * 2;
        float lo, hi;
        if (j < 64) {
            const float* e = type_embed + type_idx[n] * 64 + j;
            lo = e[0]; hi = e[1];
        } else if (j < 96) {
            const float* e = cat_embed0 + cat_idx[2 * n] * 32 + (j - 64);
            lo = e[0]; hi = e[1];
        } else if (j < 128) {
            const float* e = cat_embed1 + cat_idx[2 * n + 1] * 32 + (j - 96);
            lo = e[0]; hi = e[1];
        } else {
            int jj = j - 128;
            float d = log_deg[n];
            lo = fmaxf(d * deg_W[jj] + deg_b[jj], 0.f);
            hi = fmaxf(d * deg_W[jj + 1] + deg_b[jj + 1], 0.f);
        }
        featsb[i] = packbf(lo, hi);
        return;
    }
    int n = i - N_NODES * 80;
    if (n < N_NODES) {
        int a = 0;
#pragma unroll
        for (int j = 0; j < K_NBR; j++) a |= nbr_mask[n * K_NBR + j];
        has[n] = a ? 1 : 0;
    }
}

// ---------------- bf16 TC GEMM, 128x128 tile, x4 B-fragment loads ----------------
template <int KDIM, int MODE, bool HASBIAS>
__global__ void __launch_bounds__(256, 2)
gemm_bf16(const uint32_t* __restrict__ A, const uint32_t* __restrict__ Wpk,
          const float* __restrict__ bias, uint32_t* __restrict__ out, int ldo,
          int rows, const uint32_t* __restrict__ fbx, const int* __restrict__ fbmask)
{
    constexpr int K2  = KDIM / 2;
    constexpr int K2P = (KDIM == 160) ? 84 : 68;
    constexpr int KQ  = K2 / 4;

    extern __shared__ __align__(16) uint32_t dsm[];
    uint32_t* As = dsm;
    uint32_t* Bs = dsm + 128 * K2P;

    int t = threadIdx.x, lane = t & 31, wid = t >> 5;
    int g = lane >> 2, tig = lane & 3;
    int wm = wid & 3, wn = wid >> 2;
    int row0 = blockIdx.x * 128;
    int colbase = blockIdx.y * 128;

#pragma unroll
    for (int it = 0; it < 128 * KQ / 256; it++) {
        int i = t + it * 256;
        int r = i / KQ, q = (i - r * KQ) * 4;
        int gr = row0 + r;
        uint4 v = make_uint4(0u, 0u, 0u, 0u);
        if (gr < rows) v = *reinterpret_cast<const uint4*>(&A[(size_t)gr * K2 + q]);
        *reinterpret_cast<uint4*>(&As[r * K2P + q]) = v;
    }
#pragma unroll
    for (int it = 0; it < 128 * KQ / 256; it++) {
        int i = t + it * 256;
        int c = i / KQ, q = (i - c * KQ) * 4;
        uint4 v = *reinterpret_cast<const uint4*>(&Wpk[(size_t)(colbase + c) * K2 + q]);
        *reinterpret_cast<uint4*>(&Bs[c * K2P + q]) = v;
    }
    __syncthreads();

    uint32_t aBase = smaddr(As) + ((wm * 32 + (lane & 15)) * K2P + ((lane >> 4) << 2)) * 4;
    // B x4 map: matrices {cols cb..cb+7 × k0-7, same × k8-15, cols cb+8..15 × k0-7, same × k8-15}
    uint32_t bBase = smaddr(Bs) +
        ((wn * 64 + (lane & 7) + ((lane & 16) ? 8 : 0)) * K2P + ((lane & 8) ? 4 : 0)) * 4;

    float acc[2][8][4];
#pragma unroll
    for (int i = 0; i < 2; i++)
#pragma unroll
        for (int j = 0; j < 8; j++)
#pragma unroll
            for (int k = 0; k < 4; k++) acc[i][j][k] = 0.f;

#pragma unroll
    for (int s = 0; s < K2 / 8; s++) {
        uint32_t a[2][4];
        ldsm_x4(a[0][0], a[0][1], a[0][2], a[0][3], aBase + s * 32);
        ldsm_x4(a[1][0], a[1][1], a[1][2], a[1][3], aBase + 16 * K2P * 4 + s * 32);
#pragma unroll
        for (int ntp = 0; ntp < 4; ntp++) {
            uint32_t b0, b1, b2, b3;
            ldsm_x4(b0, b1, b2, b3, bBase + ntp * 16 * K2P * 4 + s * 32);
            mma_bf16(acc[0][2 * ntp],     a[0], b0, b1);
            mma_bf16(acc[1][2 * ntp],     a[1], b0, b1);
            mma_bf16(acc[0][2 * ntp + 1], a[0], b2, b3);
            mma_bf16(acc[1][2 * ntp + 1], a[1], b2, b3);
        }
    }

#pragma unroll
    for (int mt = 0; mt < 2; mt++) {
#pragma unroll
        for (int half = 0; half < 2; half++) {
            int gr = row0 + wm * 32 + mt * 16 + g + half * 8;
            if (gr >= rows) continue;
            bool fb = false;
            if (MODE == 2) fb = (fbmask[gr] == 0);
#pragma unroll
            for (int nt = 0; nt < 8; nt++) {
                int col = colbase + wn * 64 + nt * 8 + tig * 2;
                int pair = wn * 32 + nt * 4 + tig;
                float v0 = acc[mt][nt][half * 2 + 0];
                float v1 = acc[mt][nt][half * 2 + 1];
                if (HASBIAS) { v0 += bias[col]; v1 += bias[col + 1]; }
                if (MODE == 2) {
                    if (fb) {
                        float2 f = unpk(fbx[(size_t)gr * 64 + pair]);
                        v0 = f.x; v1 = f.y;
                    }
                    v0 = fmaxf(v0, 0.f);
                    v1 = fmaxf(v1, 0.f);
                }
                out[(size_t)gr * ldo + (colbase >> 1) + pair] = packbf(v0, v1);
            }
        }
    }
}

// ---------------- attention v3b: one warp per node, ctx split across half-warps ----------
__global__ void attn_kernel(const uint32_t* __restrict__ qkvb,
                            const int* __restrict__ nbr_idx,
                            const int* __restrict__ nbr_mask,
                            uint32_t* __restrict__ ob)
{
    int n = (blockIdx.x * blockDim.x + threadIdx.x) >> 5;
    if (n >= N_NODES) return;
    int lane = threadIdx.x & 31;
    int half = lane >> 4, hl = lane & 15;
    int p4 = hl * 4;

    uint4 qp = *reinterpret_cast<const uint4*>(&qkvb[(size_t)n * 192 + p4]);
    uint64_t q0 = upk2(qp.x), q1 = upk2(qp.y), q2 = upk2(qp.z), q3 = upk2(qp.w);

    int nb = 0, mk = 0;
    if (lane < 16) {
        nb = nbr_idx[n * K_NBR + lane];
        mk = nbr_mask[n * K_NBR + lane];
    }
    unsigned mb = __ballot_sync(0xffffffffu, (lane < 16) && mk);
    unsigned actm = (mb << 1) | 1u;

    int cbase = half * 8;
    int idxs[9];
    float sc[9];
#pragma unroll
    for (int j = 0; j < 9; j++) {
        int c = cbase + j;
        int src = (c == 0) ? 0 : (c - 1);
        int nbj = __shfl_sync(0xffffffffu, nb, src);
        int id = (c == 0) ? n : nbj;
        idxs[j] = id;
        uint4 kp = *reinterpret_cast<const uint4*>(&qkvb[(size_t)id * 192 + 64 + p4]);
        uint64_t acc = mul2(q0, upk2(kp.x));
        fma2(acc, q1, upk2(kp.y));
        fma2(acc, q2, upk2(kp.z));
        fma2(acc, q3, upk2(kp.w));
        float2 ap = unpk64(acc);
        float s = ap.x + ap.y;
        s += __shfl_xor_sync(0xffffffffu, s, 1);
        s += __shfl_xor_sync(0xffffffffu, s, 2);
        s *= 0.17677669529663687f;
        bool on = ((actm >> c) & 1) && !(half == 1 && j == 0);
        if (!on) s = -1e9f;
        sc[j] = s;
    }

    float mx = sc[0];
#pragma unroll
    for (int j = 1; j < 9; j++) mx = fmaxf(mx, sc[j]);
    mx = fmaxf(mx, __shfl_xor_sync(0xffffffffu, mx, 16));
    float den = 0.f;
#pragma unroll
    for (int j = 0; j < 9; j++) { sc[j] = __expf(sc[j] - mx); den += sc[j]; }
    den += __shfl_xor_sync(0xffffffffu, den, 16);
    float inv = 1.f / den;

    uint64_t av0 = 0, av1 = 0, av2 = 0, av3 = 0;
#pragma unroll
    for (int j = 0; j < 9; j++) {
        uint4 vp = *reinterpret_cast<const uint4*>(&qkvb[(size_t)idxs[j] * 192 + 128 + p4]);
        uint64_t pp = pk2f(sc[j], sc[j]);
        fma2(av0, pp, upk2(vp.x));
        fma2(av1, pp, upk2(vp.y));
        fma2(av2, pp, upk2(vp.z));
        fma2(av3, pp, upk2(vp.w));
    }
    float2 a0 = unpk64(av0), a1 = unpk64(av1), a2 = unpk64(av2), a3 = unpk64(av3);
    a0.x += __shfl_xor_sync(0xffffffffu, a0.x, 16);
    a0.y += __shfl_xor_sync(0xffffffffu, a0.y, 16);
    a1.x += __shfl_xor_sync(0xffffffffu, a1.x, 16);
    a1.y += __shfl_xor_sync(0xffffffffu, a1.y, 16);
    a2.x += __shfl_xor_sync(0xffffffffu, a2.x, 16);
    a2.y += __shfl_xor_sync(0xffffffffu, a2.y, 16);
    a3.x += __shfl_xor_sync(0xffffffffu, a3.x, 16);
    a3.y += __shfl_xor_sync(0xffffffffu, a3.y, 16);

    if (half == 0) {
        uint4 ov;
        ov.x = packbf(a0.x * inv, a0.y * inv);
        ov.y = packbf(a1.x * inv, a1.y * inv);
        ov.z = packbf(a2.x * inv, a2.y * inv);
        ov.w = packbf(a3.x * inv, a3.y * inv);
        *reinterpret_cast<uint4*>(&ob[(size_t)n * 64 + p4]) = ov;
    }
}

// ---------------- fused edge MLP, tf32 TC phase 2: 64 edges per block (unchanged) --------
__global__ void __launch_bounds__(256)
edge_fused_kernel(const uint32_t* __restrict__ uwb,
                  const int* __restrict__ edges,
                  const float* __restrict__ ef,
                  const float* __restrict__ eW1,
                  const float* __restrict__ eW2,
                  const float* __restrict__ eb2,
                  const float* __restrict__ eW3,
                  const float* __restrict__ eb3,
                  float* __restrict__ out)
{
    extern __shared__ __align__(16) float edsm[];
    float* W2s = edsm;                    // [128][72]
    float* h1s = edsm + 128 * 72;         // [64][132]
    float* part = h1s + 64 * 132;         // [64][2]

    int t = threadIdx.x;
    int lane = t & 31, wid = t >> 5;
    int g = lane >> 2, tig = lane & 3;
    int e0 = blockIdx.x * 64;

#pragma unroll
    for (int it = 0; it < 8; it++) {
        int i = t + it * 256;
        int k = i >> 4, c4 = (i & 15) << 2;
        float4 v = *reinterpret_cast<const float4*>(&eW2[(size_t)k * 64 + c4]);
        W2s[k * 72 + c4 + 0] = to_tf32(v.x);
        W2s[k * 72 + c4 + 1] = to_tf32(v.y);
        W2s[k * 72 + c4 + 2] = to_tf32(v.z);
        W2s[k * 72 + c4 + 3] = to_tf32(v.w);
    }

    const float* wef0 = eW1 + 256 * 128;
    const float* wef1 = eW1 + 257 * 128;
    float4 we0 = *reinterpret_cast<const float4*>(&wef0[lane * 4]);
    float4 we1 = *reinterpret_cast<const float4*>(&wef1[lane * 4]);

#pragma unroll
    for (int ee = 0; ee < 8; ee++) {
        int el = wid * 8 + ee;
        int e = e0 + el;
        int s = edges[2 * e], d = edges[2 * e + 1];
        float f0 = ef[2 * e], f1 = ef[2 * e + 1];
        uint2 up2 = *reinterpret_cast<const uint2*>(&uwb[(size_t)s * 128 + lane * 2]);
        uint2 wp2 = *reinterpret_cast<const uint2*>(&uwb[(size_t)d * 128 + 64 + lane * 2]);
        float2 ua = unpk(up2.x), ub = unpk(up2.y);
        float2 wa = unpk(wp2.x), wb = unpk(wp2.y);
        float4 h;
        h.x = to_tf32(fmaxf(ua.x + wa.x + f0 * we0.x + f1 * we1.x, 0.f));
        h.y = to_tf32(fmaxf(ua.y + wa.y + f0 * we0.y + f1 * we1.y, 0.f));
        h.z = to_tf32(fmaxf(ub.x + wb.x + f0 * we0.z + f1 * we1.z, 0.f));
        h.w = to_tf32(fmaxf(ub.y + wb.y + f0 * we0.w + f1 * we1.w, 0.f));
        *reinterpret_cast<float4*>(&h1s[el * 132 + lane * 4]) = h;
    }
    __syncthreads();

    int rb = (wid & 3) * 16;
    int cb = (wid >> 2) * 32;

    float acc[4][4];
#pragma unroll
    for (int i = 0; i < 4; i++)
#pragma unroll
        for (int j = 0; j < 4; j++) acc[i][j] = 0.f;

#pragma unroll
    for (int kb = 0; kb < 128; kb += 8) {
        uint32_t a[4];
        a[0] = __float_as_uint(h1s[(rb + g) * 132 + kb + tig]);
        a[1] = __float_as_uint(h1s[(rb + g + 8) * 132 + kb + tig]);
        a[2] = __float_as_uint(h1s[(rb + g) * 132 + kb + tig + 4]);
        a[3] = __float_as_uint(h1s[(rb + g + 8) * 132 + kb + tig + 4]);
#pragma unroll
        for (int nt = 0; nt < 4; nt++) {
            int c = cb + nt * 8 + g;
            uint32_t b0 = __float_as_uint(W2s[(kb + tig) * 72 + c]);
            uint32_t b1 = __float_as_uint(W2s[(kb + tig + 4) * 72 + c]);
            mma_tf32(acc[nt], a, b0, b1);
        }
    }

    float pg = 0.f, pg8 = 0.f;
#pragma unroll
    for (int nt = 0; nt < 4; nt++) {
        int col = cb + nt * 8 + tig * 2;
        float b20 = eb2[col], b21 = eb2[col + 1];
        float w30 = eW3[col], w31 = eW3[col + 1];
        pg  += fmaxf(acc[nt][0] + b20, 0.f) * w30 + fmaxf(acc[nt][1] + b21, 0.f) * w31;
        pg8 += fmaxf(acc[nt][2] + b20, 0.f) * w30 + fmaxf(acc[nt][3] + b21, 0.f) * w31;
    }
    pg  += __shfl_xor_sync(0xffffffffu, pg, 1);
    pg  += __shfl_xor_sync(0xffffffffu, pg, 2);
    pg8 += __shfl_xor_sync(0xffffffffu, pg8, 1);
    pg8 += __shfl_xor_sync(0xffffffffu, pg8, 2);
    if (tig == 0) {
        part[(rb + g) * 2 + (wid >> 2)]     = pg;
        part[(rb + 8 + g) * 2 + (wid >> 2)] = pg8;
    }
    __syncthreads();
    if (t < 64) out[e0 + t] = part[t * 2] + part[t * 2 + 1] + eb3[0];
}

// ---------------- launch ----------------
extern "C" void kernel_launch(void* const* d_in, const int* in_sizes, int n_in,
                              void* d_out, int out_size)
{
    (void)in_sizes; (void)n_in; (void)out_size;
    const int*   type_idx   = (const int*)d_in[0];
    const int*   cat_idx    = (const int*)d_in[1];
    const int*   nbr_idx    = (const int*)d_in[2];
    const int*   nbr_mask   = (const int*)d_in[3];
    const int*   edges      = (const int*)d_in[4];
    const float* log_deg    = (const float*)d_in[5];
    const float* edge_feats = (const float*)d_in[6];
    const float* type_embed = (const float*)d_in[7];
    const float* cat_embed0 = (const float*)d_in[8];
    const float* cat_embed1 = (const float*)d_in[9];
    const float* deg_W      = (const float*)d_in[10];
    const float* deg_b      = (const float*)d_in[11];
    const float* proj_W     = (const float*)d_in[12];
    const float* proj_b     = (const float*)d_in[13];
    const float* Wqkv       = (const float*)d_in[14];
    const float* bqkv       = (const float*)d_in[15];
    const float* Wo         = (const float*)d_in[16];
    const float* bo         = (const float*)d_in[17];
    const float* eW1        = (const float*)d_in[18];
    const float* eb1        = (const float*)d_in[19];
    const float* eW2        = (const float*)d_in[20];
    const float* eb2        = (const float*)d_in[21];
    const float* eW3        = (const float*)d_in[22];
    const float* eb3        = (const float*)d_in[23];
    float* out = (float*)d_out;

    uint32_t *featsb, *xab, *xbb, *qkvb, *ob, *uwb, *wpk;
    float* biasuw; int* has;
    cudaGetSymbolAddress((void**)&featsb, g_featsb);
    cudaGetSymbolAddress((void**)&xab, g_xab);
    cudaGetSymbolAddress((void**)&xbb, g_xbb);
    cudaGetSymbolAddress((void**)&qkvb, g_qkvb);
    cudaGetSymbolAddress((void**)&ob, g_ob);
    cudaGetSymbolAddress((void**)&uwb, g_uwb);
    cudaGetSymbolAddress((void**)&has, g_has);
    cudaGetSymbolAddress((void**)&wpk, g_wpk);
    cudaGetSymbolAddress((void**)&biasuw, g_biasuw);

    const int SM128 = 2 * 128 * 68 * 4;
    const int SM160 = 2 * 128 * 84 * 4;
    const int SMEDGE = (128 * 72 + 64 * 132 + 128) * 4;
    cudaFuncSetAttribute(gemm_bf16<160, 0, true>, cudaFuncAttributeMaxDynamicSharedMemorySize, SM160);
    cudaFuncSetAttribute(gemm_bf16<128, 0, true>, cudaFuncAttributeMaxDynamicSharedMemorySize, SM128);
    cudaFuncSetAttribute(gemm_bf16<128, 2, true>, cudaFuncAttributeMaxDynamicSharedMemorySize, SM128);
    cudaFuncSetAttribute(edge_fused_kernel, cudaFuncAttributeMaxDynamicSharedMemorySize, SMEDGE);

    prep_kernel<<<(PREP_N + 255) / 256, 256>>>(
        proj_W, Wqkv, Wo, eW1, eb1,
        type_idx, cat_idx, log_deg, type_embed, cat_embed0, cat_embed1,
        deg_W, deg_b, nbr_mask, wpk, biasuw, featsb, has);

    int gN = (N_NODES + 127) / 128;
    gemm_bf16<160, 0, true><<<gN, 256, SM160>>>(
        featsb, wpk + WPK_PROJ, proj_b, xab, 64, N_NODES, nullptr, nullptr);

    uint32_t* xcur = xab;
    uint32_t* xnxt = xbb;
    for (int l = 0; l < 3; l++) {
        gemm_bf16<128, 0, true><<<dim3(gN, 3), 256, SM128>>>(
            xcur, wpk + WPK_QKV + l * 24576, bqkv + (size_t)l * 384,
            qkvb, 192, N_NODES, nullptr, nullptr);
        attn_kernel<<<(N_NODES + 7) / 8, 256>>>(qkvb, nbr_idx, nbr_mask, ob);
        gemm_bf16<128, 2, true><<<gN, 256, SM128>>>(
            ob, wpk + WPK_WO + l * 8192, bo + (size_t)l * 128,
            xnxt, 64, N_NODES, xcur, has);
        uint32_t* tmp = xcur; xcur = xnxt; xnxt = tmp;
    }

    gemm_bf16<128, 0, true><<<dim3(gN, 2), 256, SM128>>>(
        xcur, wpk + WPK_UW, biasuw, uwb, 128, N_NODES, nullptr, nullptr);

    edge_fused_kernel<<<(N_EDGES + 63) / 64, 256, SMEDGE>>>(
        uwb, edges, edge_feats, eW1, eW2, eb2, eW3, eb3, out);
}